// round 15
// baseline (speedup 1.0000x reference)
#include <cuda_runtime.h>

#define NN    4
#define CC    20
#define HH    64
#define WWID  2048
#define KHW   5
#define PLANE (HH * WWID)     // 131072

#define TPB   128
#define TILE  256             // output px per block, 2 px/thread
#define COLS  264             // staged cols: ww = w0-4 .. w0+259
#define NV4   (COLS / 4)      // 66 float4 per row
#define CH_PER_G   2
#define NGROUPS    (CC / CH_PER_G)           // 10
#define STAGE_FLTS (CH_PER_G * KHW * COLS)   // 2640 floats per ring stage
#define NSTAGE     4                          // 42240 B total
#define SLOTS      (CH_PER_G * KHW * NV4)    // 660 float4 copies per group
#define SLOTS_FULL 5                          // 128*5 = 640
#define SLOTS_REM  (SLOTS - TPB * SLOTS_FULL) // 20 (threads 0..19)

__device__ __forceinline__ void cp_async16(void* smem, const void* gmem)
{
    unsigned saddr = (unsigned)__cvta_generic_to_shared(smem);
    asm volatile("cp.async.cg.shared.global [%0], [%1], 16;\n"
                 :: "r"(saddr), "l"(gmem));
}
__device__ __forceinline__ void cp_commit()
{
    asm volatile("cp.async.commit_group;\n" ::: "memory");
}
template <int N>
__device__ __forceinline__ void cp_wait()
{
    asm volatile("cp.async.wait_group %0;\n" :: "n"(N) : "memory");
}

__global__ __launch_bounds__(TPB, 5)
void lcxyz_kernel(const float* __restrict__ xyz,
                  const float* __restrict__ softmax,
                  const void* __restrict__ mask,
                  float* __restrict__ out)
{
    __shared__ float ring[NSTAGE * STAGE_FLTS];
    __shared__ int   sh_mode;

    const int t  = threadIdx.x;
    const int w0 = blockIdx.x * TILE;
    const int h  = blockIdx.y;
    const int n  = blockIdx.z;

    // ---- mask dtype detection (warp 0): 0=u8, 1=i32, 2=f32 ----
    if (t < 32) {
        const unsigned* m = (const unsigned*)mask;
        unsigned w1 = m[t], w2 = m[t + 32];
        bool i32ok = (w1 <= 1u) && (w2 <= 1u);
        bool f32ok = (w1 == 0u || w1 == 0x3F800000u) &&
                     (w2 == 0u || w2 == 0x3F800000u);
        unsigned bi = __ballot_sync(0xFFFFFFFFu, i32ok);
        unsigned bf = __ballot_sync(0xFFFFFFFFu, f32ok);
        if (t == 0) sh_mode = (bi == 0xFFFFFFFFu) ? 1 : ((bf == 0xFFFFFFFFu) ? 2 : 0);
    }

    int hrow[KHW];
#pragma unroll
    for (int r = 0; r < KHW; ++r)
        hrow[r] = min(max(h + r - 2, 0), HH - 1);

    const float* sm_base = softmax + (size_t)(n * CC) * PLANE;

    // ---- Precompute staging slots: 5 per thread + 1 extra for t<20 ----
    unsigned soff[SLOTS_FULL], goff[SLOTS_FULL];
    unsigned soffX = 0, goffX = 0;
    const bool hasX = (t < SLOTS_REM);
#pragma unroll
    for (int k = 0; k <= SLOTS_FULL; ++k) {
        int j = (k < SLOTS_FULL) ? (t + TPB * k) : (TPB * SLOTS_FULL + t);
        int ch  = j / (KHW * NV4);
        int rem = j - ch * (KHW * NV4);
        int rr  = rem / NV4;
        int i   = rem - rr * NV4;
        unsigned so = ch * (KHW * COLS) + rr * COLS + 4 * i;
        int gidx = hrow[rr] * WWID + (w0 - 4) + 4 * i;
        gidx = min(max(gidx, 0), PLANE - 4);     // edge garbage killed by gm=0
        unsigned go = ch * PLANE + gidx;
        if (k < SLOTS_FULL) { soff[k] = so; goff[k] = go; }
        else                { soffX   = so; goffX   = go; }
    }

    // ---- Prologue: prefetch groups 0 (stage 0) and 1 (stage 1) ----
#pragma unroll
    for (int k = 0; k < SLOTS_FULL; ++k)
        cp_async16(ring + soff[k], sm_base + goff[k]);
    if (hasX) cp_async16(ring + soffX, sm_base + goffX);
    cp_commit();
#pragma unroll
    for (int k = 0; k < SLOTS_FULL; ++k)
        cp_async16(ring + STAGE_FLTS + soff[k], sm_base + CH_PER_G * PLANE + goff[k]);
    if (hasX) cp_async16(ring + STAGE_FLTS + soffX, sm_base + CH_PER_G * PLANE + goffX);
    cp_commit();

    __syncthreads();    // sh_mode visible
    const int mmode = sh_mode;

    // ---- Phase 1: masked Gaussian weights (vectorized window loads) ----
    const int wa = w0 + 2 * t;
    const int cc = 2 * t + 4;

    const float* Xx = xyz + (size_t)n * 3 * PLANE;
    const float* Xy = Xx + PLANE;
    const float* Xz = Xy + PLANE;
    const size_t mbase = (size_t)n * PLANE;
    const unsigned char* mk_u8  = (const unsigned char*)mask + mbase;
    const int*           mk_i32 = (const int*)mask + mbase;
    const float*         mk_f32 = (const float*)mask + mbase;

    // Clamped pair-start columns (displaced values only feed zero-mask taps).
    const int c0 = max(wa - 2, 0);           // pair (s0,s1): cols wa-2, wa-1
    const int c1 = wa;                       // pair (s2,s3): cols wa,   wa+1
    const int c2 = min(wa + 2, WWID - 2);    // pair (s4,s5): cols wa+2, wa+3

    // Column validity (constant over dy); s2,s3 always valid.
    const float ok0 = (wa - 2 >= 0)   ? 1.0f : 0.0f;
    const float ok1 = (wa - 1 >= 0)   ? 1.0f : 0.0f;
    const float ok4 = (wa + 2 < WWID) ? 1.0f : 0.0f;
    const float ok5 = (wa + 3 < WWID) ? 1.0f : 0.0f;

    float cx0, cy0, cz0, cx1, cy1, cz1;      // centers, pulled from dy=2 window
    float gm0[25], gm1[25];
    float nxs[KHW][6], nys[KHW][6], nzs[KHW][6], ms[KHW][6];

#pragma unroll
    for (int dy = 0; dy < KHW; ++dy) {
        const int ro = hrow[dy] * WWID;
        const int hh = h + dy - 2;
        const float hokf = (hh >= 0 && hh < HH) ? 1.0f : 0.0f;

        float2 x01 = *(const float2*)(Xx + ro + c0);
        float2 x23 = *(const float2*)(Xx + ro + c1);
        float2 x45 = *(const float2*)(Xx + ro + c2);
        float2 y01 = *(const float2*)(Xy + ro + c0);
        float2 y23 = *(const float2*)(Xy + ro + c1);
        float2 y45 = *(const float2*)(Xy + ro + c2);
        float2 z01 = *(const float2*)(Xz + ro + c0);
        float2 z23 = *(const float2*)(Xz + ro + c1);
        float2 z45 = *(const float2*)(Xz + ro + c2);
        nxs[dy][0]=x01.x; nxs[dy][1]=x01.y; nxs[dy][2]=x23.x; nxs[dy][3]=x23.y; nxs[dy][4]=x45.x; nxs[dy][5]=x45.y;
        nys[dy][0]=y01.x; nys[dy][1]=y01.y; nys[dy][2]=y23.x; nys[dy][3]=y23.y; nys[dy][4]=y45.x; nys[dy][5]=y45.y;
        nzs[dy][0]=z01.x; nzs[dy][1]=z01.y; nzs[dy][2]=z23.x; nzs[dy][3]=z23.y; nzs[dy][4]=z45.x; nzs[dy][5]=z45.y;

        float r0, r1, r2, r3, r4, r5;
        if (mmode == 1) {
            int2 a = *(const int2*)(mk_i32 + ro + c0);
            int2 b = *(const int2*)(mk_i32 + ro + c1);
            int2 c = *(const int2*)(mk_i32 + ro + c2);
            r0 = (float)a.x; r1 = (float)a.y; r2 = (float)b.x;
            r3 = (float)b.y; r4 = (float)c.x; r5 = (float)c.y;
        } else if (mmode == 2) {
            float2 a = *(const float2*)(mk_f32 + ro + c0);
            float2 b = *(const float2*)(mk_f32 + ro + c1);
            float2 c = *(const float2*)(mk_f32 + ro + c2);
            r0 = a.x; r1 = a.y; r2 = b.x; r3 = b.y; r4 = c.x; r5 = c.y;
        } else {
            r0 = (float)mk_u8[ro + c0];     r1 = (float)mk_u8[ro + c0 + 1];
            r2 = (float)mk_u8[ro + c1];     r3 = (float)mk_u8[ro + c1 + 1];
            r4 = (float)mk_u8[ro + c2];     r5 = (float)mk_u8[ro + c2 + 1];
        }
        ms[dy][0] = r0 * ok0 * hokf;  ms[dy][1] = r1 * ok1 * hokf;
        ms[dy][2] = r2 * hokf;        ms[dy][3] = r3 * hokf;
        ms[dy][4] = r4 * ok4 * hokf;  ms[dy][5] = r5 * ok5 * hokf;
    }
    cx0 = nxs[2][2]; cy0 = nys[2][2]; cz0 = nzs[2][2];   // col wa, row h
    cx1 = nxs[2][3]; cy1 = nys[2][3]; cz1 = nzs[2][3];   // col wa+1, row h

#pragma unroll
    for (int dy = 0; dy < KHW; ++dy) {
#pragma unroll
        for (int dx = 0; dx < KHW; ++dx) {
            float ax = nxs[dy][dx] - cx0, ay = nys[dy][dx] - cy0, az = nzs[dy][dx] - cz0;
            float d2a = fmaf(ax, ax, fmaf(ay, ay, az * az));
            gm0[dy*5+dx] = ms[dy][dx] * __expf(-0.5f * d2a);
            float bx = nxs[dy][dx+1] - cx1, by = nys[dy][dx+1] - cy1, bz = nzs[dy][dx+1] - cz1;
            float d2b = fmaf(bx, bx, fmaf(by, by, bz * bz));
            gm1[dy*5+dx] = ms[dy][dx+1] * __expf(-0.5f * d2b);
        }
    }

    // ---- Phase 2: 10 groups, 4-stage ring, prefetch distance 2,
    //      two channels computed interleaved (R14 structure, unchanged). ----
    float* outp = out + ((size_t)(n * CC) * HH + h) * WWID + wa;

    for (int g = 0; g < NGROUPS; ++g) {
        if (g + 2 < NGROUPS) {
            const float* gb = sm_base + (size_t)(g + 2) * (CH_PER_G * PLANE);
            float* buf = ring + ((g + 2) & (NSTAGE - 1)) * STAGE_FLTS;
#pragma unroll
            for (int k = 0; k < SLOTS_FULL; ++k)
                cp_async16(buf + soff[k], gb + goff[k]);
            if (hasX) cp_async16(buf + soffX, gb + goffX);
            cp_commit();
            cp_wait<2>();       // group g complete; g+1, g+2 may be in flight
        } else if (g + 1 < NGROUPS) {
            cp_wait<1>();
        } else {
            cp_wait<0>();
        }
        __syncthreads();        // data visible; also fences stage reuse

        const float* B   = ring + (g & (NSTAGE - 1)) * STAGE_FLTS;
        const float* BcA = B + (cc - 2);                   // channel 0 window
        const float* BcB = B + (KHW * COLS) + (cc - 2);    // channel 1 window

        float A0e = 0.f, A0o = 0.f, A1e = 0.f, A1o = 0.f;
        float B0e = 0.f, B0o = 0.f, B1e = 0.f, B1o = 0.f;
#pragma unroll
        for (int dy = 0; dy < KHW; ++dy) {
            const float* ra = BcA + dy * COLS;
            const float* rb = BcB + dy * COLS;
            float2 a01 = *(const float2*)(ra);
            float2 b01 = *(const float2*)(rb);
            float2 a23 = *(const float2*)(ra + 2);
            float2 b23 = *(const float2*)(rb + 2);
            float2 a45 = *(const float2*)(ra + 4);
            float2 b45 = *(const float2*)(rb + 4);
            const float w0_ = gm0[dy*5+0], w1_ = gm0[dy*5+1], w2_ = gm0[dy*5+2],
                        w3_ = gm0[dy*5+3], w4_ = gm0[dy*5+4];
            const float v0_ = gm1[dy*5+0], v1_ = gm1[dy*5+1], v2_ = gm1[dy*5+2],
                        v3_ = gm1[dy*5+3], v4_ = gm1[dy*5+4];
            A0e = fmaf(w0_, a01.x, A0e);  B0e = fmaf(w0_, b01.x, B0e);
            A1e = fmaf(v0_, a01.y, A1e);  B1e = fmaf(v0_, b01.y, B1e);
            A0o = fmaf(w1_, a01.y, A0o);  B0o = fmaf(w1_, b01.y, B0o);
            A1o = fmaf(v1_, a23.x, A1o);  B1o = fmaf(v1_, b23.x, B1o);
            A0e = fmaf(w2_, a23.x, A0e);  B0e = fmaf(w2_, b23.x, B0e);
            A1e = fmaf(v2_, a23.y, A1e);  B1e = fmaf(v2_, b23.y, B1e);
            A0o = fmaf(w3_, a23.y, A0o);  B0o = fmaf(w3_, b23.y, B0o);
            A1o = fmaf(v3_, a45.x, A1o);  B1o = fmaf(v3_, b45.x, B1o);
            A0e = fmaf(w4_, a45.x, A0e);  B0e = fmaf(w4_, b45.x, B0e);
            A1e = fmaf(v4_, a45.y, A1e);  B1e = fmaf(v4_, b45.y, B1e);
        }
        const int chA = g * CH_PER_G;
        *(float2*)(outp + (size_t)(chA + 0) * PLANE) = make_float2(A0e + A0o, A1e + A1o);
        *(float2*)(outp + (size_t)(chA + 1) * PLANE) = make_float2(B0e + B0o, B1e + B1o);
        // single barrier per group: stage (g+2)%4 written above was last read
        // at iter g-2; the iter g-1 and iter g barriers separate read from write.
    }
}

extern "C" void kernel_launch(void* const* d_in, const int* in_sizes, int n_in,
                              void* d_out, int out_size)
{
    const float* xyz     = (const float*)d_in[0];
    const float* softmax = (const float*)d_in[1];
    const void*  mask    = d_in[2];
    float*       out     = (float*)d_out;

    dim3 grid(WWID / TILE, HH, NN);   // (8, 64, 4) = 2048 blocks
    dim3 block(TPB);
    lcxyz_kernel<<<grid, block>>>(xyz, softmax, mask, out);
}

// round 16
// speedup vs baseline: 1.2185x; 1.2185x over previous
#include <cuda_runtime.h>

#define NN    4
#define CC    20
#define HH    64
#define WWID  2048
#define KHW   5
#define PLANE (HH * WWID)     // 131072

#define TPB   128
#define TILE  256             // output px per block, 2 px/thread
#define COLS  264             // staged cols: ww = w0-4 .. w0+259
#define NV4   (COLS / 4)      // 66 float4 per row
#define CH_PER_G   2
#define NGROUPS    (CC / CH_PER_G)           // 10
#define STAGE_FLTS (CH_PER_G * KHW * COLS)   // 2640 floats per ring stage
#define NSTAGE     4                          // 42240 B total
#define SLOTS      (CH_PER_G * KHW * NV4)    // 660 float4 copies per group
#define SLOTS_FULL 5                          // 128*5 = 640
#define SLOTS_REM  (SLOTS - TPB * SLOTS_FULL) // 20 (threads 0..19)

__device__ __forceinline__ void cp_async16(void* smem, const void* gmem)
{
    unsigned saddr = (unsigned)__cvta_generic_to_shared(smem);
    asm volatile("cp.async.cg.shared.global [%0], [%1], 16;\n"
                 :: "r"(saddr), "l"(gmem));
}
__device__ __forceinline__ void cp_commit()
{
    asm volatile("cp.async.commit_group;\n" ::: "memory");
}
template <int N>
__device__ __forceinline__ void cp_wait()
{
    asm volatile("cp.async.wait_group %0;\n" :: "n"(N) : "memory");
}

__global__ __launch_bounds__(TPB, 5)
void lcxyz_kernel(const float* __restrict__ xyz,
                  const float* __restrict__ softmax,
                  const void* __restrict__ mask,
                  float* __restrict__ out)
{
    __shared__ float ring[NSTAGE * STAGE_FLTS];
    __shared__ int   sh_mode;

    const int t  = threadIdx.x;
    const int w0 = blockIdx.x * TILE;
    const int h  = blockIdx.y;
    const int n  = blockIdx.z;

    // ---- mask dtype detection (warp 0): 0=u8, 1=i32, 2=f32 ----
    if (t < 32) {
        const unsigned* m = (const unsigned*)mask;
        unsigned w1 = m[t], w2 = m[t + 32];
        bool i32ok = (w1 <= 1u) && (w2 <= 1u);
        bool f32ok = (w1 == 0u || w1 == 0x3F800000u) &&
                     (w2 == 0u || w2 == 0x3F800000u);
        unsigned bi = __ballot_sync(0xFFFFFFFFu, i32ok);
        unsigned bf = __ballot_sync(0xFFFFFFFFu, f32ok);
        if (t == 0) sh_mode = (bi == 0xFFFFFFFFu) ? 1 : ((bf == 0xFFFFFFFFu) ? 2 : 0);
    }

    int hrow[KHW];
#pragma unroll
    for (int r = 0; r < KHW; ++r)
        hrow[r] = min(max(h + r - 2, 0), HH - 1);

    const float* sm_base = softmax + (size_t)(n * CC) * PLANE;

    // ---- Precompute staging slots: 5 per thread + 1 extra for t<20 ----
    unsigned soff[SLOTS_FULL], goff[SLOTS_FULL];
    unsigned soffX = 0, goffX = 0;
    const bool hasX = (t < SLOTS_REM);
#pragma unroll
    for (int k = 0; k <= SLOTS_FULL; ++k) {
        int j = (k < SLOTS_FULL) ? (t + TPB * k) : (TPB * SLOTS_FULL + t);
        int ch  = j / (KHW * NV4);
        int rem = j - ch * (KHW * NV4);
        int rr  = rem / NV4;
        int i   = rem - rr * NV4;
        unsigned so = ch * (KHW * COLS) + rr * COLS + 4 * i;
        int gidx = hrow[rr] * WWID + (w0 - 4) + 4 * i;
        gidx = min(max(gidx, 0), PLANE - 4);     // edge garbage killed by gm=0
        unsigned go = ch * PLANE + gidx;
        if (k < SLOTS_FULL) { soff[k] = so; goff[k] = go; }
        else                { soffX   = so; goffX   = go; }
    }

    // ---- Prologue: prefetch groups 0 (stage 0) and 1 (stage 1) ----
#pragma unroll
    for (int k = 0; k < SLOTS_FULL; ++k)
        cp_async16(ring + soff[k], sm_base + goff[k]);
    if (hasX) cp_async16(ring + soffX, sm_base + goffX);
    cp_commit();
#pragma unroll
    for (int k = 0; k < SLOTS_FULL; ++k)
        cp_async16(ring + STAGE_FLTS + soff[k], sm_base + CH_PER_G * PLANE + goff[k]);
    if (hasX) cp_async16(ring + STAGE_FLTS + soffX, sm_base + CH_PER_G * PLANE + goffX);
    cp_commit();

    __syncthreads();    // sh_mode visible
    const int mmode = sh_mode;

    // ---- Phase 1: masked Gaussian weights (per-dy vectorized loads, no
    //      persistent arrays -> no spills) ----
    const int wa = w0 + 2 * t;
    const int cc = 2 * t + 4;

    const float* Xx = xyz + (size_t)n * 3 * PLANE;
    const float* Xy = Xx + PLANE;
    const float* Xz = Xy + PLANE;
    const size_t mbase = (size_t)n * PLANE;
    const unsigned char* mk_u8  = (const unsigned char*)mask + mbase;
    const int*           mk_i32 = (const int*)mask + mbase;
    const float*         mk_f32 = (const float*)mask + mbase;

    // Clamped pair-start columns (displaced values only feed zero-mask taps).
    const int c0 = max(wa - 2, 0);           // pair (s0,s1): cols wa-2, wa-1
    const int c1 = wa;                       // pair (s2,s3): cols wa,   wa+1
    const int c2 = min(wa + 2, WWID - 2);    // pair (s4,s5): cols wa+2, wa+3

    // Column validity factors (constant over dy); middle pair always valid.
    const float ok0 = (wa - 2 >= 0)   ? 1.0f : 0.0f;
    const float ok1 = (wa - 1 >= 0)   ? 1.0f : 0.0f;
    const float ok4 = (wa + 2 < WWID) ? 1.0f : 0.0f;
    const float ok5 = (wa + 3 < WWID) ? 1.0f : 0.0f;

    const float cx0 = Xx[h * WWID + wa],     cy0 = Xy[h * WWID + wa],     cz0 = Xz[h * WWID + wa];
    const float cx1 = Xx[h * WWID + wa + 1], cy1 = Xy[h * WWID + wa + 1], cz1 = Xz[h * WWID + wa + 1];

    float gm0[25], gm1[25];
#pragma unroll
    for (int dy = 0; dy < KHW; ++dy) {
        const int ro = hrow[dy] * WWID;
        const int hh = h + dy - 2;
        const float hokf = (hh >= 0 && hh < HH) ? 1.0f : 0.0f;

        float2 x01 = *(const float2*)(Xx + ro + c0);
        float2 x23 = *(const float2*)(Xx + ro + c1);
        float2 x45 = *(const float2*)(Xx + ro + c2);
        float2 y01 = *(const float2*)(Xy + ro + c0);
        float2 y23 = *(const float2*)(Xy + ro + c1);
        float2 y45 = *(const float2*)(Xy + ro + c2);
        float2 z01 = *(const float2*)(Xz + ro + c0);
        float2 z23 = *(const float2*)(Xz + ro + c1);
        float2 z45 = *(const float2*)(Xz + ro + c2);
        float nx[6] = { x01.x, x01.y, x23.x, x23.y, x45.x, x45.y };
        float ny[6] = { y01.x, y01.y, y23.x, y23.y, y45.x, y45.y };
        float nz[6] = { z01.x, z01.y, z23.x, z23.y, z45.x, z45.y };

        float r0, r1, r2, r3, r4, r5;
        if (mmode == 1) {
            int2 a = *(const int2*)(mk_i32 + ro + c0);
            int2 b = *(const int2*)(mk_i32 + ro + c1);
            int2 c = *(const int2*)(mk_i32 + ro + c2);
            r0 = (float)a.x; r1 = (float)a.y; r2 = (float)b.x;
            r3 = (float)b.y; r4 = (float)c.x; r5 = (float)c.y;
        } else if (mmode == 2) {
            float2 a = *(const float2*)(mk_f32 + ro + c0);
            float2 b = *(const float2*)(mk_f32 + ro + c1);
            float2 c = *(const float2*)(mk_f32 + ro + c2);
            r0 = a.x; r1 = a.y; r2 = b.x; r3 = b.y; r4 = c.x; r5 = c.y;
        } else {
            r0 = (float)mk_u8[ro + c0];     r1 = (float)mk_u8[ro + c0 + 1];
            r2 = (float)mk_u8[ro + c1];     r3 = (float)mk_u8[ro + c1 + 1];
            r4 = (float)mk_u8[ro + c2];     r5 = (float)mk_u8[ro + c2 + 1];
        }
        float m[6];
        m[0] = r0 * ok0 * hokf;  m[1] = r1 * ok1 * hokf;
        m[2] = r2 * hokf;        m[3] = r3 * hokf;
        m[4] = r4 * ok4 * hokf;  m[5] = r5 * ok5 * hokf;

#pragma unroll
        for (int dx = 0; dx < KHW; ++dx) {
            float ax = nx[dx] - cx0, ay = ny[dx] - cy0, az = nz[dx] - cz0;
            float d2a = fmaf(ax, ax, fmaf(ay, ay, az * az));
            gm0[dy*5+dx] = m[dx] * __expf(-0.5f * d2a);
            float bx = nx[dx+1] - cx1, by = ny[dx+1] - cy1, bz = nz[dx+1] - cz1;
            float d2b = fmaf(bx, bx, fmaf(by, by, bz * bz));
            gm1[dy*5+dx] = m[dx+1] * __expf(-0.5f * d2b);
        }
    }

    // ---- Phase 2: 10 groups, 4-stage ring, prefetch distance 2,
    //      two channels computed interleaved (R14 structure, unchanged). ----
    float* outp = out + ((size_t)(n * CC) * HH + h) * WWID + wa;

    for (int g = 0; g < NGROUPS; ++g) {
        if (g + 2 < NGROUPS) {
            const float* gb = sm_base + (size_t)(g + 2) * (CH_PER_G * PLANE);
            float* buf = ring + ((g + 2) & (NSTAGE - 1)) * STAGE_FLTS;
#pragma unroll
            for (int k = 0; k < SLOTS_FULL; ++k)
                cp_async16(buf + soff[k], gb + goff[k]);
            if (hasX) cp_async16(buf + soffX, gb + goffX);
            cp_commit();
            cp_wait<2>();       // group g complete; g+1, g+2 may be in flight
        } else if (g + 1 < NGROUPS) {
            cp_wait<1>();
        } else {
            cp_wait<0>();
        }
        __syncthreads();        // data visible; also fences stage reuse

        const float* B   = ring + (g & (NSTAGE - 1)) * STAGE_FLTS;
        const float* BcA = B + (cc - 2);                   // channel 0 window
        const float* BcB = B + (KHW * COLS) + (cc - 2);    // channel 1 window

        float A0e = 0.f, A0o = 0.f, A1e = 0.f, A1o = 0.f;
        float B0e = 0.f, B0o = 0.f, B1e = 0.f, B1o = 0.f;
#pragma unroll
        for (int dy = 0; dy < KHW; ++dy) {
            const float* ra = BcA + dy * COLS;
            const float* rb = BcB + dy * COLS;
            float2 a01 = *(const float2*)(ra);
            float2 b01 = *(const float2*)(rb);
            float2 a23 = *(const float2*)(ra + 2);
            float2 b23 = *(const float2*)(rb + 2);
            float2 a45 = *(const float2*)(ra + 4);
            float2 b45 = *(const float2*)(rb + 4);
            const float w0_ = gm0[dy*5+0], w1_ = gm0[dy*5+1], w2_ = gm0[dy*5+2],
                        w3_ = gm0[dy*5+3], w4_ = gm0[dy*5+4];
            const float v0_ = gm1[dy*5+0], v1_ = gm1[dy*5+1], v2_ = gm1[dy*5+2],
                        v3_ = gm1[dy*5+3], v4_ = gm1[dy*5+4];
            A0e = fmaf(w0_, a01.x, A0e);  B0e = fmaf(w0_, b01.x, B0e);
            A1e = fmaf(v0_, a01.y, A1e);  B1e = fmaf(v0_, b01.y, B1e);
            A0o = fmaf(w1_, a01.y, A0o);  B0o = fmaf(w1_, b01.y, B0o);
            A1o = fmaf(v1_, a23.x, A1o);  B1o = fmaf(v1_, b23.x, B1o);
            A0e = fmaf(w2_, a23.x, A0e);  B0e = fmaf(w2_, b23.x, B0e);
            A1e = fmaf(v2_, a23.y, A1e);  B1e = fmaf(v2_, b23.y, B1e);
            A0o = fmaf(w3_, a23.y, A0o);  B0o = fmaf(w3_, b23.y, B0o);
            A1o = fmaf(v3_, a45.x, A1o);  B1o = fmaf(v3_, b45.x, B1o);
            A0e = fmaf(w4_, a45.x, A0e);  B0e = fmaf(w4_, b45.x, B0e);
            A1e = fmaf(v4_, a45.y, A1e);  B1e = fmaf(v4_, b45.y, B1e);
        }
        const int chA = g * CH_PER_G;
        *(float2*)(outp + (size_t)(chA + 0) * PLANE) = make_float2(A0e + A0o, A1e + A1o);
        *(float2*)(outp + (size_t)(chA + 1) * PLANE) = make_float2(B0e + B0o, B1e + B1o);
        // single barrier per group: stage (g+2)%4 written above was last read
        // at iter g-2; the iter g-1 and iter g barriers separate read from write.
    }
}

extern "C" void kernel_launch(void* const* d_in, const int* in_sizes, int n_in,
                              void* d_out, int out_size)
{
    const float* xyz     = (const float*)d_in[0];
    const float* softmax = (const float*)d_in[1];
    const void*  mask    = d_in[2];
    float*       out     = (float*)d_out;

    dim3 grid(WWID / TILE, HH, NN);   // (8, 64, 4) = 2048 blocks
    dim3 block(TPB);
    lcxyz_kernel<<<grid, block>>>(xyz, softmax, mask, out);
}

// round 17
// speedup vs baseline: 1.5285x; 1.2545x over previous
#include <cuda_runtime.h>

#define NN    4
#define CC    20
#define HH    64
#define WWID  2048
#define KHW   5
#define PLANE (HH * WWID)     // 131072

#define TPB    128
#define TW     64             // tile width (px); warp covers one row, 2 px/lane
#define TH     4              // tile height (rows); 4 warps = 4 rows
#define SROWS  (TH + 4)       // 8 staged rows (h0-2 .. h0+5)
#define SCOLS  72             // staged cols (w0-4 .. w0+67), 18 float4
#define SNV4   (SCOLS / 4)    // 18
#define CH_PER_G   2
#define NGROUPS    (CC / CH_PER_G)              // 10
#define CH_FLTS    (SROWS * SCOLS)              // 576 floats per channel
#define STAGE_FLTS (CH_PER_G * CH_FLTS)         // 1152 floats per ring stage
#define NSTAGE     4                             // 18432 B total
#define SLOTS      (CH_PER_G * SROWS * SNV4)    // 288 float4 copies per group
#define SL_FULL    2                             // 128*2 = 256
#define SL_REM     (SLOTS - TPB * SL_FULL)       // 32 (threads 0..31)

__device__ __forceinline__ void cp_async16(void* smem, const void* gmem)
{
    unsigned saddr = (unsigned)__cvta_generic_to_shared(smem);
    asm volatile("cp.async.cg.shared.global [%0], [%1], 16;\n"
                 :: "r"(saddr), "l"(gmem));
}
__device__ __forceinline__ void cp_commit()
{
    asm volatile("cp.async.commit_group;\n" ::: "memory");
}
template <int N>
__device__ __forceinline__ void cp_wait()
{
    asm volatile("cp.async.wait_group %0;\n" :: "n"(N) : "memory");
}

__global__ __launch_bounds__(TPB, 5)
void lcxyz_kernel(const float* __restrict__ xyz,
                  const float* __restrict__ softmax,
                  const void* __restrict__ mask,
                  float* __restrict__ out)
{
    __shared__ float ring[NSTAGE * STAGE_FLTS];
    __shared__ int   sh_mode;

    const int t  = threadIdx.x;
    const int w0 = blockIdx.x * TW;
    const int h0 = blockIdx.y * TH;
    const int n  = blockIdx.z;

    const int tr   = t >> 5;        // thread's row within tile (0..3)
    const int lane = t & 31;
    const int hth  = h0 + tr;       // thread's output row
    const int wa   = w0 + 2 * lane; // thread's pixel 0; pixel 1 = wa+1

    // ---- mask dtype detection (warp 0): 0=u8, 1=i32, 2=f32 ----
    if (t < 32) {
        const unsigned* m = (const unsigned*)mask;
        unsigned w1 = m[t], w2 = m[t + 32];
        bool i32ok = (w1 <= 1u) && (w2 <= 1u);
        bool f32ok = (w1 == 0u || w1 == 0x3F800000u) &&
                     (w2 == 0u || w2 == 0x3F800000u);
        unsigned bi = __ballot_sync(0xFFFFFFFFu, i32ok);
        unsigned bf = __ballot_sync(0xFFFFFFFFu, f32ok);
        if (t == 0) sh_mode = (bi == 0xFFFFFFFFu) ? 1 : ((bf == 0xFFFFFFFFu) ? 2 : 0);
    }

    const float* sm_base = softmax + (size_t)(n * CC) * PLANE;

    // ---- Precompute staging slots: 2 per thread + 1 extra for t<32 ----
    // Staged rows rr=0..7 represent global rows clamp(h0+rr-2).
    unsigned soff[SL_FULL], goff[SL_FULL];
    unsigned soffX = 0, goffX = 0;
    const bool hasX = (t < SL_REM);
#pragma unroll
    for (int k = 0; k <= SL_FULL; ++k) {
        int j = (k < SL_FULL) ? (t + TPB * k) : (TPB * SL_FULL + t);
        int ch  = j / (SROWS * SNV4);
        int rem = j - ch * (SROWS * SNV4);
        int rr  = rem / SNV4;
        int i   = rem - rr * SNV4;
        unsigned so = ch * CH_FLTS + rr * SCOLS + 4 * i;
        int grow = min(max(h0 + rr - 2, 0), HH - 1);
        int gcol = min(max(w0 - 4 + 4 * i, 0), WWID - 4);  // edge garbage killed by gm=0
        unsigned go = ch * PLANE + grow * WWID + gcol;
        if (k < SL_FULL) { soff[k] = so; goff[k] = go; }
        else             { soffX   = so; goffX   = go; }
    }

    // ---- Prologue: prefetch groups 0 (stage 0) and 1 (stage 1) ----
#pragma unroll
    for (int k = 0; k < SL_FULL; ++k)
        cp_async16(ring + soff[k], sm_base + goff[k]);
    if (hasX) cp_async16(ring + soffX, sm_base + goffX);
    cp_commit();
#pragma unroll
    for (int k = 0; k < SL_FULL; ++k)
        cp_async16(ring + STAGE_FLTS + soff[k], sm_base + CH_PER_G * PLANE + goff[k]);
    if (hasX) cp_async16(ring + STAGE_FLTS + soffX, sm_base + CH_PER_G * PLANE + goffX);
    cp_commit();

    __syncthreads();    // sh_mode visible
    const int mmode = sh_mode;

    // ---- Phase 1: masked Gaussian weights (per-dy vectorized loads) ----
    int hrow[KHW];
#pragma unroll
    for (int r = 0; r < KHW; ++r)
        hrow[r] = min(max(hth + r - 2, 0), HH - 1);

    const float* Xx = xyz + (size_t)n * 3 * PLANE;
    const float* Xy = Xx + PLANE;
    const float* Xz = Xy + PLANE;
    const size_t mbase = (size_t)n * PLANE;
    const unsigned char* mk_u8  = (const unsigned char*)mask + mbase;
    const int*           mk_i32 = (const int*)mask + mbase;
    const float*         mk_f32 = (const float*)mask + mbase;

    // Clamped pair-start columns (displaced values only feed zero-mask taps).
    const int c0 = max(wa - 2, 0);
    const int c1 = wa;
    const int c2 = min(wa + 2, WWID - 2);
    const float ok0 = (wa - 2 >= 0)   ? 1.0f : 0.0f;
    const float ok1 = (wa - 1 >= 0)   ? 1.0f : 0.0f;
    const float ok4 = (wa + 2 < WWID) ? 1.0f : 0.0f;
    const float ok5 = (wa + 3 < WWID) ? 1.0f : 0.0f;

    const float cx0 = Xx[hth * WWID + wa],     cy0 = Xy[hth * WWID + wa],     cz0 = Xz[hth * WWID + wa];
    const float cx1 = Xx[hth * WWID + wa + 1], cy1 = Xy[hth * WWID + wa + 1], cz1 = Xz[hth * WWID + wa + 1];

    float gm0[25], gm1[25];
#pragma unroll
    for (int dy = 0; dy < KHW; ++dy) {
        const int ro = hrow[dy] * WWID;
        const int hh = hth + dy - 2;
        const float hokf = (hh >= 0 && hh < HH) ? 1.0f : 0.0f;

        float2 x01 = *(const float2*)(Xx + ro + c0);
        float2 x23 = *(const float2*)(Xx + ro + c1);
        float2 x45 = *(const float2*)(Xx + ro + c2);
        float2 y01 = *(const float2*)(Xy + ro + c0);
        float2 y23 = *(const float2*)(Xy + ro + c1);
        float2 y45 = *(const float2*)(Xy + ro + c2);
        float2 z01 = *(const float2*)(Xz + ro + c0);
        float2 z23 = *(const float2*)(Xz + ro + c1);
        float2 z45 = *(const float2*)(Xz + ro + c2);
        float nx[6] = { x01.x, x01.y, x23.x, x23.y, x45.x, x45.y };
        float ny[6] = { y01.x, y01.y, y23.x, y23.y, y45.x, y45.y };
        float nz[6] = { z01.x, z01.y, z23.x, z23.y, z45.x, z45.y };

        float r0, r1, r2, r3, r4, r5;
        if (mmode == 1) {
            int2 a = *(const int2*)(mk_i32 + ro + c0);
            int2 b = *(const int2*)(mk_i32 + ro + c1);
            int2 c = *(const int2*)(mk_i32 + ro + c2);
            r0 = (float)a.x; r1 = (float)a.y; r2 = (float)b.x;
            r3 = (float)b.y; r4 = (float)c.x; r5 = (float)c.y;
        } else if (mmode == 2) {
            float2 a = *(const float2*)(mk_f32 + ro + c0);
            float2 b = *(const float2*)(mk_f32 + ro + c1);
            float2 c = *(const float2*)(mk_f32 + ro + c2);
            r0 = a.x; r1 = a.y; r2 = b.x; r3 = b.y; r4 = c.x; r5 = c.y;
        } else {
            r0 = (float)mk_u8[ro + c0];     r1 = (float)mk_u8[ro + c0 + 1];
            r2 = (float)mk_u8[ro + c1];     r3 = (float)mk_u8[ro + c1 + 1];
            r4 = (float)mk_u8[ro + c2];     r5 = (float)mk_u8[ro + c2 + 1];
        }
        float m[6];
        m[0] = r0 * ok0 * hokf;  m[1] = r1 * ok1 * hokf;
        m[2] = r2 * hokf;        m[3] = r3 * hokf;
        m[4] = r4 * ok4 * hokf;  m[5] = r5 * ok5 * hokf;

#pragma unroll
        for (int dx = 0; dx < KHW; ++dx) {
            float ax = nx[dx] - cx0, ay = ny[dx] - cy0, az = nz[dx] - cz0;
            float d2a = fmaf(ax, ax, fmaf(ay, ay, az * az));
            gm0[dy*5+dx] = m[dx] * __expf(-0.5f * d2a);
            float bx = nx[dx+1] - cx1, by = ny[dx+1] - cy1, bz = nz[dx+1] - cz1;
            float d2b = fmaf(bx, bx, fmaf(by, by, bz * bz));
            gm1[dy*5+dx] = m[dx+1] * __expf(-0.5f * d2b);
        }
    }

    // ---- Phase 2: 10 groups, 4-stage ring, prefetch distance 2,
    //      interleaved channel pair (R16 pipeline, 2-D tile consume). ----
    // Thread's window: stage row tr+dy, stage col 2*lane+2 (8B aligned).
    const int wbase = tr * SCOLS + 2 * lane + 2;   // offset of window start at dy=0
    float* outp = out + ((size_t)(n * CC) * HH + hth) * WWID + wa;

    for (int g = 0; g < NGROUPS; ++g) {
        if (g + 2 < NGROUPS) {
            const float* gb = sm_base + (size_t)(g + 2) * (CH_PER_G * PLANE);
            float* buf = ring + ((g + 2) & (NSTAGE - 1)) * STAGE_FLTS;
#pragma unroll
            for (int k = 0; k < SL_FULL; ++k)
                cp_async16(buf + soff[k], gb + goff[k]);
            if (hasX) cp_async16(buf + soffX, gb + goffX);
            cp_commit();
            cp_wait<2>();       // group g complete; g+1, g+2 may be in flight
        } else if (g + 1 < NGROUPS) {
            cp_wait<1>();
        } else {
            cp_wait<0>();
        }
        __syncthreads();        // data visible; also fences stage reuse

        const float* B   = ring + (g & (NSTAGE - 1)) * STAGE_FLTS;
        const float* BcA = B + wbase;              // channel 0 window
        const float* BcB = B + CH_FLTS + wbase;    // channel 1 window

        float A0e = 0.f, A0o = 0.f, A1e = 0.f, A1o = 0.f;
        float B0e = 0.f, B0o = 0.f, B1e = 0.f, B1o = 0.f;
#pragma unroll
        for (int dy = 0; dy < KHW; ++dy) {
            const float* ra = BcA + dy * SCOLS;
            const float* rb = BcB + dy * SCOLS;
            float2 a01 = *(const float2*)(ra);
            float2 b01 = *(const float2*)(rb);
            float2 a23 = *(const float2*)(ra + 2);
            float2 b23 = *(const float2*)(rb + 2);
            float2 a45 = *(const float2*)(ra + 4);
            float2 b45 = *(const float2*)(rb + 4);
            const float w0_ = gm0[dy*5+0], w1_ = gm0[dy*5+1], w2_ = gm0[dy*5+2],
                        w3_ = gm0[dy*5+3], w4_ = gm0[dy*5+4];
            const float v0_ = gm1[dy*5+0], v1_ = gm1[dy*5+1], v2_ = gm1[dy*5+2],
                        v3_ = gm1[dy*5+3], v4_ = gm1[dy*5+4];
            A0e = fmaf(w0_, a01.x, A0e);  B0e = fmaf(w0_, b01.x, B0e);
            A1e = fmaf(v0_, a01.y, A1e);  B1e = fmaf(v0_, b01.y, B1e);
            A0o = fmaf(w1_, a01.y, A0o);  B0o = fmaf(w1_, b01.y, B0o);
            A1o = fmaf(v1_, a23.x, A1o);  B1o = fmaf(v1_, b23.x, B1o);
            A0e = fmaf(w2_, a23.x, A0e);  B0e = fmaf(w2_, b23.x, B0e);
            A1e = fmaf(v2_, a23.y, A1e);  B1e = fmaf(v2_, b23.y, B1e);
            A0o = fmaf(w3_, a23.y, A0o);  B0o = fmaf(w3_, b23.y, B0o);
            A1o = fmaf(v3_, a45.x, A1o);  B1o = fmaf(v3_, b45.x, B1o);
            A0e = fmaf(w4_, a45.x, A0e);  B0e = fmaf(w4_, b45.x, B0e);
            A1e = fmaf(v4_, a45.y, A1e);  B1e = fmaf(v4_, b45.y, B1e);
        }
        const int chA = g * CH_PER_G;
        *(float2*)(outp + (size_t)(chA + 0) * PLANE) = make_float2(A0e + A0o, A1e + A1o);
        *(float2*)(outp + (size_t)(chA + 1) * PLANE) = make_float2(B0e + B0o, B1e + B1o);
        // single barrier per group: stage (g+2)%4 written above was last read
        // at iter g-2; the iter g-1 and iter g barriers separate read from write.
    }
}

extern "C" void kernel_launch(void* const* d_in, const int* in_sizes, int n_in,
                              void* d_out, int out_size)
{
    const float* xyz     = (const float*)d_in[0];
    const float* softmax = (const float*)d_in[1];
    const void*  mask    = d_in[2];
    float*       out     = (float*)d_out;

    dim3 grid(WWID / TW, HH / TH, NN);   // (32, 16, 4) = 2048 blocks
    dim3 block(TPB);
    lcxyz_kernel<<<grid, block>>>(xyz, softmax, mask, out);
}